// round 14
// baseline (speedup 1.0000x reference)
#include <cuda_runtime.h>
#include <cstdint>

// ---------------------------------------------------------------------------
// HandGNNEncoder: 2-layer GCN over fixed 21-node skeleton + mean pool.
//   y[t] = (A_norm @ x)[t]; p = c^T relu(y@W1+b1); out = p@W2 + b2
// Stages 1-2: scalar fp32. Stage 3: mma.sync bf16 hi/lo 3-pass (tensor).
// R14 = R11 structure (early block sync, pair-local A handoff, occ-3/regs-80)
// but single kernel: W2 -> bf16 hi/lo conversion done in-kernel (cheap),
// no serialized prep launch.
// ---------------------------------------------------------------------------

#define R2  0.70710678118654752440f
#define R3  0.57735026918962576451f
#define TH  (1.0f/3.0f)
#define W23 (R2*R3)

__device__ __constant__ float cPool[21] = {
    (1.0f + 2.0f*R2 + 3.0f*R3)/21.0f,
    1.0f/21.0f, 1.0f/21.0f, 1.0f/21.0f, 0.5f/21.0f,
    (1.0f + W23)/21.0f,      1.0f/21.0f, 1.0f/21.0f, 0.5f/21.0f,
    (2.0f/3.0f + W23)/21.0f, 1.0f/21.0f, 1.0f/21.0f, 0.5f/21.0f,
    (2.0f/3.0f + W23)/21.0f, 1.0f/21.0f, 1.0f/21.0f, 0.5f/21.0f,
    (1.0f/3.0f + W23)/21.0f, 1.0f/21.0f, 1.0f/21.0f, 0.5f/21.0f,
};
__device__ __constant__ int cIdx[63] = {
    0,0,0,   1,0,0,   2,1,0,   3,2,0,   4,3,0,
    5,0,0,   6,5,0,   7,6,0,   8,7,0,
    9,0,5,   10,9,0,  11,10,0, 12,11,0,
    13,0,9,  14,13,0, 15,14,0, 16,15,0,
    17,0,13, 18,17,0, 19,18,0, 20,19,0
};
__device__ __constant__ float cWt[63] = {
    1.0f,0.f,0.f,   0.5f,R2,0.f,   0.5f,0.5f,0.f, 0.5f,0.5f,0.f, 0.5f,0.5f,0.f,
    0.5f,R2,0.f,    0.5f,0.5f,0.f, 0.5f,0.5f,0.f, 0.5f,0.5f,0.f,
    TH,R3,W23,      0.5f,W23,0.f,  0.5f,0.5f,0.f, 0.5f,0.5f,0.f,
    TH,R3,TH,       0.5f,W23,0.f,  0.5f,0.5f,0.f, 0.5f,0.5f,0.f,
    TH,R3,TH,       0.5f,W23,0.f,  0.5f,0.5f,0.f, 0.5f,0.5f,0.f
};

#define NWARP 8
#define THREADS 256
#define FULLMASK 0xffffffffu

__device__ __forceinline__ uint32_t pkbf(float up, float lo) {
    uint32_t r;
    asm("cvt.rn.bf16x2.f32 %0, %1, %2;" : "=r"(r) : "f"(up), "f"(lo));
    return r;
}
__device__ __forceinline__ float bflo_f(uint32_t p) { return __uint_as_float(p << 16); }
__device__ __forceinline__ float bfhi_f(uint32_t p) { return __uint_as_float(p & 0xffff0000u); }

__device__ __forceinline__ uint32_t smem_u32(const void* p) {
    uint32_t a;
    asm("{ .reg .u64 t; cvta.to.shared.u64 t, %1; cvt.u32.u64 %0, t; }"
        : "=r"(a) : "l"(p));
    return a;
}
__device__ __forceinline__ void ldsm_x4(uint32_t* r, uint32_t addr) {
    asm volatile("ldmatrix.sync.aligned.m8n8.x4.shared.b16 {%0,%1,%2,%3}, [%4];"
                 : "=r"(r[0]), "=r"(r[1]), "=r"(r[2]), "=r"(r[3]) : "r"(addr));
}
__device__ __forceinline__ void ldsm_x4t(uint32_t* r, uint32_t addr) {
    asm volatile("ldmatrix.sync.aligned.m8n8.x4.trans.shared.b16 {%0,%1,%2,%3}, [%4];"
                 : "=r"(r[0]), "=r"(r[1]), "=r"(r[2]), "=r"(r[3]) : "r"(addr));
}
__device__ __forceinline__ void mma16816(float* d, const uint32_t* a,
                                         uint32_t b0, uint32_t b1) {
    asm volatile(
        "mma.sync.aligned.m16n8k16.row.col.f32.bf16.bf16.f32 "
        "{%0,%1,%2,%3}, {%4,%5,%6,%7}, {%8,%9}, {%0,%1,%2,%3};"
        : "+f"(d[0]), "+f"(d[1]), "+f"(d[2]), "+f"(d[3])
        : "r"(a[0]), "r"(a[1]), "r"(a[2]), "r"(a[3]), "r"(b0), "r"(b1));
}

// dynamic smem offsets (bytes)
#define OFF_WHI 0                       // W2 hi bf16 [64][128] swizzled, 16KB
#define OFF_WLO 16384                   // W2 lo, 16KB
#define OFF_A   32768                   // 4 pair-tiles x 4KB (hi 2K + lo 2K)
#define OFF_Y   49152                   // per-warp yx/yy: 8 x 1344B
#define DYN_SMEM 59904

__global__ __launch_bounds__(256, 3)
void gnn_kernel(const float* __restrict__ x,
                const float* __restrict__ W1,
                const float* __restrict__ b1,
                const float* __restrict__ W2,
                const float* __restrict__ b2,
                float* __restrict__ out,
                int G)
{
    extern __shared__ __align__(16) char smp[];
    const uint32_t sbase = smem_u32(smp);

    const int tid  = threadIdx.x;
    const int lane = tid & 31;
    const int warp = tid >> 5;
    const int pair = warp >> 1;            // 0..3: m16 tile within CTA
    const int half = warp & 1;             // which 8 rows of the tile

    const int gt0 = (blockIdx.x * 4 + pair) * 16;   // pair's 16-graph tile
    const int g0  = gt0 + half * 8;                 // warp's 8 graphs

    // ---- prefetch x for the 8 graphs (overlaps W2 conversion) ----
    float2 xv[8];
    #pragma unroll
    for (int j = 0; j < 8; j++) {
        const int g = g0 + j;
        xv[j] = (lane < 21 && g < G)
                ? ((const float2*)x)[(size_t)g * 21 + lane]
                : make_float2(0.f, 0.f);
    }

    // ---- W2 -> bf16 hi/lo into swizzled smem [k][n], 256B rows (in-kernel) ----
    #pragma unroll
    for (int it = 0; it < 16; it++) {
        const int i = tid + it * THREADS;            // 0..4095 (pairs)
        const int k = i >> 6, n2 = i & 63;
        const float2 f = ((const float2*)W2)[i];
        const uint32_t hp = pkbf(f.y, f.x);
        const float rx = f.x - bflo_f(hp);
        const float ry = f.y - bfhi_f(hp);
        const uint32_t lp = pkbf(ry, rx);
        const uint32_t off = (uint32_t)k * 256 + (((uint32_t)n2 * 4) ^ ((k & 7) << 4));
        *(uint32_t*)(smp + OFF_WHI + off) = hp;
        *(uint32_t*)(smp + OFF_WLO + off) = lp;
    }
    __syncthreads();   // W2 smem ready (early; stages 1-2 don't touch it)

    // per-lane W1/b1: lane owns dims d0=2*lane, d1=2*lane+1
    const float w10a = W1[2*lane],      w11a = W1[64 + 2*lane];
    const float w10b = W1[2*lane + 1],  w11b = W1[65 + 2*lane];
    const float b1a  = b1[2*lane],      b1b  = b1[2*lane + 1];

    // stage-1 sparse row of this lane (lane == target node t)
    int s0 = 0, s1 = 0, s2 = 0;
    float aw0 = 0.f, aw1 = 0.f, aw2 = 0.f;
    if (lane < 21) {
        s0  = cIdx[lane*3];  s1  = cIdx[lane*3+1];  s2  = cIdx[lane*3+2];
        aw0 = cWt[lane*3];   aw1 = cWt[lane*3+1];   aw2 = cWt[lane*3+2];
    }

    float* const yx = (float*)(smp + OFF_Y) + warp * 336;    // [21][8]
    float* const yy = yx + 168;

    // ---- stage 1: y = A_norm @ x via shuffles (2 quads) ----
    #pragma unroll
    for (int h = 0; h < 2; h++) {
        float ax[4], ay[4];
        #pragma unroll
        for (int j = 0; j < 4; j++) {
            const float2 v = xv[4*h + j];
            float xs0x = __shfl_sync(FULLMASK, v.x, s0);
            float xs0y = __shfl_sync(FULLMASK, v.y, s0);
            float xs1x = __shfl_sync(FULLMASK, v.x, s1);
            float xs1y = __shfl_sync(FULLMASK, v.y, s1);
            float xs2x = __shfl_sync(FULLMASK, v.x, s2);
            float xs2y = __shfl_sync(FULLMASK, v.y, s2);
            ax[j] = fmaf(aw2, xs2x, fmaf(aw1, xs1x, aw0 * xs0x));
            ay[j] = fmaf(aw2, xs2y, fmaf(aw1, xs1y, aw0 * xs0y));
        }
        if (lane < 21) {
            *(float4*)&yx[lane * 8 + 4*h] = make_float4(ax[0], ax[1], ax[2], ax[3]);
            *(float4*)&yy[lane * 8 + 4*h] = make_float4(ay[0], ay[1], ay[2], ay[3]);
        }
    }
    __syncwarp();

    // ---- stage 2: p[g][d0..d1] = sum_t c_t relu(y@W1+b1), 8 graphs ----
    float p0[8], p1[8];
    #pragma unroll
    for (int g = 0; g < 8; g++) { p0[g] = 0.f; p1[g] = 0.f; }

    #pragma unroll 3
    for (int t = 0; t < 21; t++) {
        const float ct = cPool[t];
        float4 qx[2], qy[2];
        #pragma unroll
        for (int q = 0; q < 2; q++) {
            qx[q] = *(const float4*)&yx[t * 8 + 4*q];
            qy[q] = *(const float4*)&yy[t * 8 + 4*q];
        }
        #pragma unroll
        for (int q = 0; q < 2; q++) {
            const float xs[4] = {qx[q].x, qx[q].y, qx[q].z, qx[q].w};
            const float ys[4] = {qy[q].x, qy[q].y, qy[q].z, qy[q].w};
            #pragma unroll
            for (int j = 0; j < 4; j++) {
                const int g = 4*q + j;
                float ha = fmaf(ys[j], w11a, fmaf(xs[j], w10a, b1a));
                ha = fmaxf(ha, 0.f);
                p0[g] = fmaf(ct, ha, p0[g]);
                float hb = fmaf(ys[j], w11b, fmaf(xs[j], w10b, b1b));
                hb = fmaxf(hb, 0.f);
                p1[g] = fmaf(ct, hb, p1[g]);
            }
        }
    }

    // ---- write warp's 8 rows of the pair A tile (bf16 hi/lo, swizzled) ----
    {
        char* const Ahi = smp + OFF_A + pair * 4096;
        char* const Alo = Ahi + 2048;
        #pragma unroll
        for (int j = 0; j < 8; j++) {
            const int row = half * 8 + j;
            const uint32_t hp = pkbf(p1[j], p0[j]);
            const float r0 = p0[j] - bflo_f(hp);
            const float r1 = p1[j] - bfhi_f(hp);
            const uint32_t lp = pkbf(r1, r0);
            const uint32_t off = (uint32_t)row * 128 + (((uint32_t)lane * 4) ^ ((row & 7) << 4));
            *(uint32_t*)(Ahi + off) = hp;
            *(uint32_t*)(Alo + off) = lp;
        }
    }
    // pair-local handoff: only the 2 warps of this pair sync
    asm volatile("bar.sync %0, %1;" :: "r"(1 + pair), "r"(64) : "memory");

    // ---- stage 3: pair tile out[16x128]; this warp does its n-half ----
    uint32_t ahi[4][4], alo[4][4];
    {
        const uint32_t m = lane & 15, ch = (lane >> 4);
        const uint32_t arow = m * 128;
        const uint32_t abase_hi = sbase + OFF_A + pair * 4096;
        const uint32_t abase_lo = abase_hi + 2048;
        #pragma unroll
        for (int kt = 0; kt < 4; kt++) {
            const uint32_t kb = (uint32_t)kt * 32 + ch * 16;
            const uint32_t off = arow + (kb ^ ((m & 7) << 4));
            ldsm_x4(ahi[kt], abase_hi + off);
            ldsm_x4(alo[kt], abase_lo + off);
        }
    }

    // B x4.trans lane addressing
    const uint32_t mg    = (uint32_t)lane >> 3;
    const uint32_t krow  = ((uint32_t)lane & 7) + ((mg & 1) << 3);
    const uint32_t nhalf = (mg >> 1) << 4;
    const uint32_t wbase_hi = sbase + OFF_WHI;
    const uint32_t wbase_lo = sbase + OFF_WLO;
    const int gr0 = gt0 + (lane >> 2);
    const int gr1 = gr0 + 8;
    const int ncol = (lane & 3) * 2;

    #pragma unroll
    for (int i = 0; i < 4; i++) {                   // this warp's 4 n16-tile pairs
        const int ntp = half * 4 + i;
        float d0[4] = {0.f, 0.f, 0.f, 0.f};
        float d1[4] = {0.f, 0.f, 0.f, 0.f};
        const uint32_t nb = (uint32_t)ntp * 32 + nhalf;
        #pragma unroll
        for (int kt = 0; kt < 4; kt++) {
            const uint32_t k = (uint32_t)kt * 16 + krow;
            const uint32_t off = k * 256 + (nb ^ ((k & 7) << 4));
            uint32_t bh[4], bl[4];
            ldsm_x4t(bh, wbase_hi + off);
            ldsm_x4t(bl, wbase_lo + off);
            mma16816(d0, ahi[kt], bh[0], bh[1]);
            mma16816(d1, ahi[kt], bh[2], bh[3]);
            mma16816(d0, alo[kt], bh[0], bh[1]);
            mma16816(d1, alo[kt], bh[2], bh[3]);
            mma16816(d0, ahi[kt], bl[0], bl[1]);
            mma16816(d1, ahi[kt], bl[2], bl[3]);
        }
        const int c0 = ntp * 16 + ncol;
        const float2 bb0 = __ldg((const float2*)(b2 + c0));
        const float2 bb1 = __ldg((const float2*)(b2 + c0 + 8));
        if (gr0 < G) {
            *(float2*)(out + (size_t)gr0 * 128 + c0)     = make_float2(d0[0] + bb0.x, d0[1] + bb0.y);
            *(float2*)(out + (size_t)gr0 * 128 + c0 + 8) = make_float2(d1[0] + bb1.x, d1[1] + bb1.y);
        }
        if (gr1 < G) {
            *(float2*)(out + (size_t)gr1 * 128 + c0)     = make_float2(d0[2] + bb0.x, d0[3] + bb0.y);
            *(float2*)(out + (size_t)gr1 * 128 + c0 + 8) = make_float2(d1[2] + bb1.x, d1[3] + bb1.y);
        }
    }
}

extern "C" void kernel_launch(void* const* d_in, const int* in_sizes, int n_in,
                              void* d_out, int out_size) {
    const float* x  = (const float*)d_in[0];
    const float* W1 = (const float*)d_in[1];
    const float* b1 = (const float*)d_in[2];
    const float* W2 = (const float*)d_in[3];
    const float* b2 = (const float*)d_in[4];
    float* out = (float*)d_out;

    const int G = in_sizes[0] / 42;              // graphs = B*S = 32768
    const int blocks = (G + 63) / 64;            // 64 graphs/CTA -> 512

    static int attr_set = 0;
    if (!attr_set) {
        cudaFuncSetAttribute(gnn_kernel,
                             cudaFuncAttributeMaxDynamicSharedMemorySize, DYN_SMEM);
        attr_set = 1;
    }
    gnn_kernel<<<blocks, THREADS, DYN_SMEM>>>(x, W1, b1, W2, b2, out, G);
}

// round 15
// speedup vs baseline: 1.6154x; 1.6154x over previous
#include <cuda_runtime.h>
#include <cstdint>

// ---------------------------------------------------------------------------
// HandGNNEncoder: 2-layer GCN over fixed 21-node skeleton + mean pool.
//   y[t] = (A_norm @ x)[t]; p = c^T relu(y@W1+b1); out = p@W2 + b2
// Stages 1-2: scalar fp32. Stage 3: mma.sync bf16 hi/lo 3-pass (tensor).
// R15 = R11 main kernel, but the W2 pre-split runs inside the SAME launch:
// CTAs 0..15 each convert 1/16 of W2 into a __device__ image and set a bit
// in a ready-mask; everyone acquires the mask before the raw 32KB smem copy.
// No second kernel launch.
// ---------------------------------------------------------------------------

#define R2  0.70710678118654752440f
#define R3  0.57735026918962576451f
#define TH  (1.0f/3.0f)
#define W23 (R2*R3)

__device__ __constant__ float cPool[21] = {
    (1.0f + 2.0f*R2 + 3.0f*R3)/21.0f,
    1.0f/21.0f, 1.0f/21.0f, 1.0f/21.0f, 0.5f/21.0f,
    (1.0f + W23)/21.0f,      1.0f/21.0f, 1.0f/21.0f, 0.5f/21.0f,
    (2.0f/3.0f + W23)/21.0f, 1.0f/21.0f, 1.0f/21.0f, 0.5f/21.0f,
    (2.0f/3.0f + W23)/21.0f, 1.0f/21.0f, 1.0f/21.0f, 0.5f/21.0f,
    (1.0f/3.0f + W23)/21.0f, 1.0f/21.0f, 1.0f/21.0f, 0.5f/21.0f,
};
__device__ __constant__ int cIdx[63] = {
    0,0,0,   1,0,0,   2,1,0,   3,2,0,   4,3,0,
    5,0,0,   6,5,0,   7,6,0,   8,7,0,
    9,0,5,   10,9,0,  11,10,0, 12,11,0,
    13,0,9,  14,13,0, 15,14,0, 16,15,0,
    17,0,13, 18,17,0, 19,18,0, 20,19,0
};
__device__ __constant__ float cWt[63] = {
    1.0f,0.f,0.f,   0.5f,R2,0.f,   0.5f,0.5f,0.f, 0.5f,0.5f,0.f, 0.5f,0.5f,0.f,
    0.5f,R2,0.f,    0.5f,0.5f,0.f, 0.5f,0.5f,0.f, 0.5f,0.5f,0.f,
    TH,R3,W23,      0.5f,W23,0.f,  0.5f,0.5f,0.f, 0.5f,0.5f,0.f,
    TH,R3,TH,       0.5f,W23,0.f,  0.5f,0.5f,0.f, 0.5f,0.5f,0.f,
    TH,R3,TH,       0.5f,W23,0.f,  0.5f,0.5f,0.f, 0.5f,0.5f,0.f
};

#define NWARP 8
#define THREADS 256
#define FULLMASK 0xffffffffu

__device__ __forceinline__ uint32_t pkbf(float up, float lo) {
    uint32_t r;
    asm("cvt.rn.bf16x2.f32 %0, %1, %2;" : "=r"(r) : "f"(up), "f"(lo));
    return r;
}
__device__ __forceinline__ float bflo_f(uint32_t p) { return __uint_as_float(p << 16); }
__device__ __forceinline__ float bfhi_f(uint32_t p) { return __uint_as_float(p & 0xffff0000u); }

__device__ __forceinline__ uint32_t smem_u32(const void* p) {
    uint32_t a;
    asm("{ .reg .u64 t; cvta.to.shared.u64 t, %1; cvt.u32.u64 %0, t; }"
        : "=r"(a) : "l"(p));
    return a;
}
__device__ __forceinline__ void ldsm_x4(uint32_t* r, uint32_t addr) {
    asm volatile("ldmatrix.sync.aligned.m8n8.x4.shared.b16 {%0,%1,%2,%3}, [%4];"
                 : "=r"(r[0]), "=r"(r[1]), "=r"(r[2]), "=r"(r[3]) : "r"(addr));
}
__device__ __forceinline__ void ldsm_x4t(uint32_t* r, uint32_t addr) {
    asm volatile("ldmatrix.sync.aligned.m8n8.x4.trans.shared.b16 {%0,%1,%2,%3}, [%4];"
                 : "=r"(r[0]), "=r"(r[1]), "=r"(r[2]), "=r"(r[3]) : "r"(addr));
}
__device__ __forceinline__ void mma16816(float* d, const uint32_t* a,
                                         uint32_t b0, uint32_t b1) {
    asm volatile(
        "mma.sync.aligned.m16n8k16.row.col.f32.bf16.bf16.f32 "
        "{%0,%1,%2,%3}, {%4,%5,%6,%7}, {%8,%9}, {%0,%1,%2,%3};"
        : "+f"(d[0]), "+f"(d[1]), "+f"(d[2]), "+f"(d[3])
        : "r"(a[0]), "r"(a[1]), "r"(a[2]), "r"(a[3]), "r"(b0), "r"(b1));
}

// Pre-split W2 image: [0..4095] hi words, [4096..8191] lo words, in the
// swizzled [k][n] 256B-row smem layout (word = k*64 + (n2 ^ ((k&7)<<2))).
__device__ uint32_t gW2[8192];
__device__ uint32_t gReady;     // bit c set once producer CTA c has published

// dynamic smem (bytes)
#define OFF_WHI 0                       // W2 hi bf16 [64][128] swizzled, 16KB
#define OFF_WLO 16384                   // W2 lo, 16KB
#define OFF_A   32768                   // 4 pair-tiles x 4KB (hi 2K + lo 2K)
#define OFF_Y   49152                   // per-warp yx/yy: 8 x 1344B
#define DYN_SMEM 59904

__global__ __launch_bounds__(256, 3)
void gnn_kernel(const float* __restrict__ x,
                const float* __restrict__ W1,
                const float* __restrict__ b1,
                const float* __restrict__ W2,
                const float* __restrict__ b2,
                float* __restrict__ out,
                int G)
{
    extern __shared__ __align__(16) char smp[];
    const uint32_t sbase = smem_u32(smp);

    const int tid  = threadIdx.x;
    const int lane = tid & 31;
    const int warp = tid >> 5;
    const int pair = warp >> 1;            // 0..3: m16 tile within CTA
    const int half = warp & 1;             // which 8 rows of the tile

    const int gt0 = (blockIdx.x * 4 + pair) * 16;   // pair's 16-graph tile
    const int g0  = gt0 + half * 8;                 // warp's 8 graphs

    // ---- prefetch x for the 8 graphs (overlaps producer work / wait) ----
    float2 xv[8];
    #pragma unroll
    for (int j = 0; j < 8; j++) {
        const int g = g0 + j;
        xv[j] = (lane < 21 && g < G)
                ? ((const float2*)x)[(size_t)g * 21 + lane]
                : make_float2(0.f, 0.f);
    }

    // ---- producer CTAs 0..15: convert 256 W2 pairs each into gW2 ----
    if (blockIdx.x < 16) {
        const int i = blockIdx.x * 256 + tid;       // 0..4095
        const int k = i >> 6, n2 = i & 63;
        const float2 f = ((const float2*)W2)[i];
        const uint32_t hp = pkbf(f.y, f.x);
        const float rx = f.x - bflo_f(hp);
        const float ry = f.y - bfhi_f(hp);
        const uint32_t lp = pkbf(ry, rx);
        const uint32_t w = (uint32_t)k * 64 + ((uint32_t)n2 ^ (((uint32_t)k & 7) << 2));
        gW2[w]        = hp;
        gW2[4096 + w] = lp;
        __syncthreads();
        __threadfence();
        if (tid == 0) atomicOr(&gReady, 1u << blockIdx.x);
    }

    // ---- wait until the full gW2 image is published (all 16 bits) ----
    if (tid == 0) {
        uint32_t v;
        do {
            asm volatile("ld.acquire.gpu.u32 %0, [%1];" : "=r"(v) : "l"(&gReady));
        } while ((v & 0xFFFFu) != 0xFFFFu);
    }
    __syncthreads();

    // ---- stage W2 hi/lo: raw vector copy of pre-split image (32KB) ----
    {
        const uint4* __restrict__ gsrc = (const uint4*)gW2;
        uint4* gdst = (uint4*)(smp + OFF_WHI);
        #pragma unroll
        for (int i = 0; i < 8; i++)
            gdst[tid + i * THREADS] = gsrc[tid + i * THREADS];
    }
    __syncthreads();   // W2 smem ready (early; stages 1-2 don't touch it)

    // per-lane W1/b1: lane owns dims d0=2*lane, d1=2*lane+1
    const float w10a = W1[2*lane],      w11a = W1[64 + 2*lane];
    const float w10b = W1[2*lane + 1],  w11b = W1[65 + 2*lane];
    const float b1a  = b1[2*lane],      b1b  = b1[2*lane + 1];

    // stage-1 sparse row of this lane (lane == target node t)
    int s0 = 0, s1 = 0, s2 = 0;
    float aw0 = 0.f, aw1 = 0.f, aw2 = 0.f;
    if (lane < 21) {
        s0  = cIdx[lane*3];  s1  = cIdx[lane*3+1];  s2  = cIdx[lane*3+2];
        aw0 = cWt[lane*3];   aw1 = cWt[lane*3+1];   aw2 = cWt[lane*3+2];
    }

    float* const yx = (float*)(smp + OFF_Y) + warp * 336;    // [21][8]
    float* const yy = yx + 168;

    // ---- stage 1: y = A_norm @ x via shuffles (2 quads) ----
    #pragma unroll
    for (int h = 0; h < 2; h++) {
        float ax[4], ay[4];
        #pragma unroll
        for (int j = 0; j < 4; j++) {
            const float2 v = xv[4*h + j];
            float xs0x = __shfl_sync(FULLMASK, v.x, s0);
            float xs0y = __shfl_sync(FULLMASK, v.y, s0);
            float xs1x = __shfl_sync(FULLMASK, v.x, s1);
            float xs1y = __shfl_sync(FULLMASK, v.y, s1);
            float xs2x = __shfl_sync(FULLMASK, v.x, s2);
            float xs2y = __shfl_sync(FULLMASK, v.y, s2);
            ax[j] = fmaf(aw2, xs2x, fmaf(aw1, xs1x, aw0 * xs0x));
            ay[j] = fmaf(aw2, xs2y, fmaf(aw1, xs1y, aw0 * xs0y));
        }
        if (lane < 21) {
            *(float4*)&yx[lane * 8 + 4*h] = make_float4(ax[0], ax[1], ax[2], ax[3]);
            *(float4*)&yy[lane * 8 + 4*h] = make_float4(ay[0], ay[1], ay[2], ay[3]);
        }
    }
    __syncwarp();

    // ---- stage 2: p[g][d0..d1] = sum_t c_t relu(y@W1+b1), 8 graphs ----
    float p0[8], p1[8];
    #pragma unroll
    for (int g = 0; g < 8; g++) { p0[g] = 0.f; p1[g] = 0.f; }

    #pragma unroll 3
    for (int t = 0; t < 21; t++) {
        const float ct = cPool[t];
        float4 qx[2], qy[2];
        #pragma unroll
        for (int q = 0; q < 2; q++) {
            qx[q] = *(const float4*)&yx[t * 8 + 4*q];
            qy[q] = *(const float4*)&yy[t * 8 + 4*q];
        }
        #pragma unroll
        for (int q = 0; q < 2; q++) {
            const float xs[4] = {qx[q].x, qx[q].y, qx[q].z, qx[q].w};
            const float ys[4] = {qy[q].x, qy[q].y, qy[q].z, qy[q].w};
            #pragma unroll
            for (int j = 0; j < 4; j++) {
                const int g = 4*q + j;
                float ha = fmaf(ys[j], w11a, fmaf(xs[j], w10a, b1a));
                ha = fmaxf(ha, 0.f);
                p0[g] = fmaf(ct, ha, p0[g]);
                float hb = fmaf(ys[j], w11b, fmaf(xs[j], w10b, b1b));
                hb = fmaxf(hb, 0.f);
                p1[g] = fmaf(ct, hb, p1[g]);
            }
        }
    }

    // ---- write warp's 8 rows of the pair A tile (bf16 hi/lo, swizzled) ----
    {
        char* const Ahi = smp + OFF_A + pair * 4096;
        char* const Alo = Ahi + 2048;
        #pragma unroll
        for (int j = 0; j < 8; j++) {
            const int row = half * 8 + j;
            const uint32_t hp = pkbf(p1[j], p0[j]);
            const float r0 = p0[j] - bflo_f(hp);
            const float r1 = p1[j] - bfhi_f(hp);
            const uint32_t lp = pkbf(r1, r0);
            const uint32_t off = (uint32_t)row * 128 + (((uint32_t)lane * 4) ^ ((row & 7) << 4));
            *(uint32_t*)(Ahi + off) = hp;
            *(uint32_t*)(Alo + off) = lp;
        }
    }
    // pair-local handoff: only the 2 warps of this pair sync
    asm volatile("bar.sync %0, %1;" :: "r"(1 + pair), "r"(64) : "memory");

    // ---- stage 3: pair tile out[16x128]; this warp does its n-half ----
    uint32_t ahi[4][4], alo[4][4];
    {
        const uint32_t m = lane & 15, ch = (lane >> 4);
        const uint32_t arow = m * 128;
        const uint32_t abase_hi = sbase + OFF_A + pair * 4096;
        const uint32_t abase_lo = abase_hi + 2048;
        #pragma unroll
        for (int kt = 0; kt < 4; kt++) {
            const uint32_t kb = (uint32_t)kt * 32 + ch * 16;
            const uint32_t off = arow + (kb ^ ((m & 7) << 4));
            ldsm_x4(ahi[kt], abase_hi + off);
            ldsm_x4(alo[kt], abase_lo + off);
        }
    }

    // B x4.trans lane addressing
    const uint32_t mg    = (uint32_t)lane >> 3;
    const uint32_t krow  = ((uint32_t)lane & 7) + ((mg & 1) << 3);
    const uint32_t nhalf = (mg >> 1) << 4;
    const uint32_t wbase_hi = sbase + OFF_WHI;
    const uint32_t wbase_lo = sbase + OFF_WLO;
    const int gr0 = gt0 + (lane >> 2);
    const int gr1 = gr0 + 8;
    const int ncol = (lane & 3) * 2;

    #pragma unroll
    for (int i = 0; i < 4; i++) {                   // this warp's 4 n16-tile pairs
        const int ntp = half * 4 + i;
        float d0[4] = {0.f, 0.f, 0.f, 0.f};
        float d1[4] = {0.f, 0.f, 0.f, 0.f};
        const uint32_t nb = (uint32_t)ntp * 32 + nhalf;
        #pragma unroll
        for (int kt = 0; kt < 4; kt++) {
            const uint32_t k = (uint32_t)kt * 16 + krow;
            const uint32_t off = k * 256 + (nb ^ ((k & 7) << 4));
            uint32_t bh[4], bl[4];
            ldsm_x4t(bh, wbase_hi + off);
            ldsm_x4t(bl, wbase_lo + off);
            mma16816(d0, ahi[kt], bh[0], bh[1]);
            mma16816(d1, ahi[kt], bh[2], bh[3]);
            mma16816(d0, alo[kt], bh[0], bh[1]);
            mma16816(d1, alo[kt], bh[2], bh[3]);
            mma16816(d0, ahi[kt], bl[0], bl[1]);
            mma16816(d1, ahi[kt], bl[2], bl[3]);
        }
        const int c0 = ntp * 16 + ncol;
        const float2 bb0 = __ldg((const float2*)(b2 + c0));
        const float2 bb1 = __ldg((const float2*)(b2 + c0 + 8));
        if (gr0 < G) {
            *(float2*)(out + (size_t)gr0 * 128 + c0)     = make_float2(d0[0] + bb0.x, d0[1] + bb0.y);
            *(float2*)(out + (size_t)gr0 * 128 + c0 + 8) = make_float2(d1[0] + bb1.x, d1[1] + bb1.y);
        }
        if (gr1 < G) {
            *(float2*)(out + (size_t)gr1 * 128 + c0)     = make_float2(d0[2] + bb0.x, d0[3] + bb0.y);
            *(float2*)(out + (size_t)gr1 * 128 + c0 + 8) = make_float2(d1[2] + bb1.x, d1[3] + bb1.y);
        }
    }
}

extern "C" void kernel_launch(void* const* d_in, const int* in_sizes, int n_in,
                              void* d_out, int out_size) {
    const float* x  = (const float*)d_in[0];
    const float* W1 = (const float*)d_in[1];
    const float* b1 = (const float*)d_in[2];
    const float* W2 = (const float*)d_in[3];
    const float* b2 = (const float*)d_in[4];
    float* out = (float*)d_out;

    const int G = in_sizes[0] / 42;              // graphs = B*S = 32768
    const int blocks = (G + 63) / 64;            // 64 graphs/CTA -> 512

    static int attr_set = 0;
    if (!attr_set) {
        cudaFuncSetAttribute(gnn_kernel,
                             cudaFuncAttributeMaxDynamicSharedMemorySize, DYN_SMEM);
        attr_set = 1;
    }
    gnn_kernel<<<blocks, THREADS, DYN_SMEM>>>(x, W1, b1, W2, b2, out, G);
}

// round 16
// speedup vs baseline: 1.7371x; 1.0753x over previous
#include <cuda_runtime.h>
#include <cstdint>

// ---------------------------------------------------------------------------
// HandGNNEncoder: 2-layer GCN over fixed 21-node skeleton + mean pool.
//   y[t] = (A_norm @ x)[t]; p = c^T relu(y@W1+b1); out = p@W2 + b2
// Stages 1-2: scalar fp32. Stage 3: mma.sync bf16 hi/lo 3-pass (tensor).
// R16 = R15 (fused producer CTAs pre-split W2 into gW2 + ready mask), but
// the 32KB gW2->smem staging is cp.async overlapped with stages 1-2; the
// single wait+barrier sits after the A-tile write.
// ---------------------------------------------------------------------------

#define R2  0.70710678118654752440f
#define R3  0.57735026918962576451f
#define TH  (1.0f/3.0f)
#define W23 (R2*R3)

__device__ __constant__ float cPool[21] = {
    (1.0f + 2.0f*R2 + 3.0f*R3)/21.0f,
    1.0f/21.0f, 1.0f/21.0f, 1.0f/21.0f, 0.5f/21.0f,
    (1.0f + W23)/21.0f,      1.0f/21.0f, 1.0f/21.0f, 0.5f/21.0f,
    (2.0f/3.0f + W23)/21.0f, 1.0f/21.0f, 1.0f/21.0f, 0.5f/21.0f,
    (2.0f/3.0f + W23)/21.0f, 1.0f/21.0f, 1.0f/21.0f, 0.5f/21.0f,
    (1.0f/3.0f + W23)/21.0f, 1.0f/21.0f, 1.0f/21.0f, 0.5f/21.0f,
};
__device__ __constant__ int cIdx[63] = {
    0,0,0,   1,0,0,   2,1,0,   3,2,0,   4,3,0,
    5,0,0,   6,5,0,   7,6,0,   8,7,0,
    9,0,5,   10,9,0,  11,10,0, 12,11,0,
    13,0,9,  14,13,0, 15,14,0, 16,15,0,
    17,0,13, 18,17,0, 19,18,0, 20,19,0
};
__device__ __constant__ float cWt[63] = {
    1.0f,0.f,0.f,   0.5f,R2,0.f,   0.5f,0.5f,0.f, 0.5f,0.5f,0.f, 0.5f,0.5f,0.f,
    0.5f,R2,0.f,    0.5f,0.5f,0.f, 0.5f,0.5f,0.f, 0.5f,0.5f,0.f,
    TH,R3,W23,      0.5f,W23,0.f,  0.5f,0.5f,0.f, 0.5f,0.5f,0.f,
    TH,R3,TH,       0.5f,W23,0.f,  0.5f,0.5f,0.f, 0.5f,0.5f,0.f,
    TH,R3,TH,       0.5f,W23,0.f,  0.5f,0.5f,0.f, 0.5f,0.5f,0.f
};

#define NWARP 8
#define THREADS 256
#define FULLMASK 0xffffffffu

__device__ __forceinline__ uint32_t pkbf(float up, float lo) {
    uint32_t r;
    asm("cvt.rn.bf16x2.f32 %0, %1, %2;" : "=r"(r) : "f"(up), "f"(lo));
    return r;
}
__device__ __forceinline__ float bflo_f(uint32_t p) { return __uint_as_float(p << 16); }
__device__ __forceinline__ float bfhi_f(uint32_t p) { return __uint_as_float(p & 0xffff0000u); }

__device__ __forceinline__ uint32_t smem_u32(const void* p) {
    uint32_t a;
    asm("{ .reg .u64 t; cvta.to.shared.u64 t, %1; cvt.u32.u64 %0, t; }"
        : "=r"(a) : "l"(p));
    return a;
}
__device__ __forceinline__ void ldsm_x4(uint32_t* r, uint32_t addr) {
    asm volatile("ldmatrix.sync.aligned.m8n8.x4.shared.b16 {%0,%1,%2,%3}, [%4];"
                 : "=r"(r[0]), "=r"(r[1]), "=r"(r[2]), "=r"(r[3]) : "r"(addr));
}
__device__ __forceinline__ void ldsm_x4t(uint32_t* r, uint32_t addr) {
    asm volatile("ldmatrix.sync.aligned.m8n8.x4.trans.shared.b16 {%0,%1,%2,%3}, [%4];"
                 : "=r"(r[0]), "=r"(r[1]), "=r"(r[2]), "=r"(r[3]) : "r"(addr));
}
__device__ __forceinline__ void mma16816(float* d, const uint32_t* a,
                                         uint32_t b0, uint32_t b1) {
    asm volatile(
        "mma.sync.aligned.m16n8k16.row.col.f32.bf16.bf16.f32 "
        "{%0,%1,%2,%3}, {%4,%5,%6,%7}, {%8,%9}, {%0,%1,%2,%3};"
        : "+f"(d[0]), "+f"(d[1]), "+f"(d[2]), "+f"(d[3])
        : "r"(a[0]), "r"(a[1]), "r"(a[2]), "r"(a[3]), "r"(b0), "r"(b1));
}
__device__ __forceinline__ void cp_async16(uint32_t sdst, const void* gsrc) {
    asm volatile("cp.async.cg.shared.global [%0], [%1], 16;"
                 :: "r"(sdst), "l"(gsrc) : "memory");
}

// Pre-split W2 image: [0..4095] hi words, [4096..8191] lo words, in the
// swizzled [k][n] 256B-row smem layout (word = k*64 + (n2 ^ ((k&7)<<2))).
__device__ uint32_t gW2[8192];
__device__ uint32_t gReady;     // bit c set once producer CTA c has published

// dynamic smem (bytes)
#define OFF_WHI 0                       // W2 hi bf16 [64][128] swizzled, 16KB
#define OFF_WLO 16384                   // W2 lo, 16KB
#define OFF_A   32768                   // 4 pair-tiles x 4KB (hi 2K + lo 2K)
#define OFF_Y   49152                   // per-warp yx/yy: 8 x 1344B
#define DYN_SMEM 59904

__global__ __launch_bounds__(256, 3)
void gnn_kernel(const float* __restrict__ x,
                const float* __restrict__ W1,
                const float* __restrict__ b1,
                const float* __restrict__ W2,
                const float* __restrict__ b2,
                float* __restrict__ out,
                int G)
{
    extern __shared__ __align__(16) char smp[];
    const uint32_t sbase = smem_u32(smp);

    const int tid  = threadIdx.x;
    const int lane = tid & 31;
    const int warp = tid >> 5;
    const int pair = warp >> 1;            // 0..3: m16 tile within CTA
    const int half = warp & 1;             // which 8 rows of the tile

    const int gt0 = (blockIdx.x * 4 + pair) * 16;   // pair's 16-graph tile
    const int g0  = gt0 + half * 8;                 // warp's 8 graphs

    // ---- prefetch x for the 8 graphs (overlaps producer work) ----
    float2 xv[8];
    #pragma unroll
    for (int j = 0; j < 8; j++) {
        const int g = g0 + j;
        xv[j] = (lane < 21 && g < G)
                ? ((const float2*)x)[(size_t)g * 21 + lane]
                : make_float2(0.f, 0.f);
    }

    // ---- producer CTAs 0..15: convert 256 W2 pairs each into gW2 ----
    if (blockIdx.x < 16) {
        const int i = blockIdx.x * 256 + tid;       // 0..4095
        const int k = i >> 6, n2 = i & 63;
        const float2 f = ((const float2*)W2)[i];
        const uint32_t hp = pkbf(f.y, f.x);
        const float rx = f.x - bflo_f(hp);
        const float ry = f.y - bfhi_f(hp);
        const uint32_t lp = pkbf(ry, rx);
        const uint32_t w = (uint32_t)k * 64 + ((uint32_t)n2 ^ (((uint32_t)k & 7) << 2));
        gW2[w]        = hp;
        gW2[4096 + w] = lp;
        __syncthreads();
        __threadfence();
        if (tid == 0) atomicOr(&gReady, 1u << blockIdx.x);
    }

    // ---- per-thread acquire-poll on the ready mask (uniform addr) ----
    {
        uint32_t v;
        do {
            asm volatile("ld.acquire.gpu.u32 %0, [%1];" : "=r"(v) : "l"(&gReady));
        } while ((v & 0xFFFFu) != 0xFFFFu);
    }

    // ---- launch async W2 staging (32KB); drains during stages 1-2 ----
    {
        const char* gsrc = (const char*)gW2;
        #pragma unroll
        for (int i = 0; i < 8; i++) {
            const int off = (tid + i * THREADS) * 16;
            cp_async16(sbase + OFF_WHI + off, gsrc + off);
        }
        asm volatile("cp.async.commit_group;" ::: "memory");
    }

    // per-lane W1/b1: lane owns dims d0=2*lane, d1=2*lane+1
    const float w10a = W1[2*lane],      w11a = W1[64 + 2*lane];
    const float w10b = W1[2*lane + 1],  w11b = W1[65 + 2*lane];
    const float b1a  = b1[2*lane],      b1b  = b1[2*lane + 1];

    // stage-1 sparse row of this lane (lane == target node t)
    int s0 = 0, s1 = 0, s2 = 0;
    float aw0 = 0.f, aw1 = 0.f, aw2 = 0.f;
    if (lane < 21) {
        s0  = cIdx[lane*3];  s1  = cIdx[lane*3+1];  s2  = cIdx[lane*3+2];
        aw0 = cWt[lane*3];   aw1 = cWt[lane*3+1];   aw2 = cWt[lane*3+2];
    }

    float* const yx = (float*)(smp + OFF_Y) + warp * 336;    // [21][8]
    float* const yy = yx + 168;

    // ---- stage 1: y = A_norm @ x via shuffles (2 quads) ----
    #pragma unroll
    for (int h = 0; h < 2; h++) {
        float ax[4], ay[4];
        #pragma unroll
        for (int j = 0; j < 4; j++) {
            const float2 v = xv[4*h + j];
            float xs0x = __shfl_sync(FULLMASK, v.x, s0);
            float xs0y = __shfl_sync(FULLMASK, v.y, s0);
            float xs1x = __shfl_sync(FULLMASK, v.x, s1);
            float xs1y = __shfl_sync(FULLMASK, v.y, s1);
            float xs2x = __shfl_sync(FULLMASK, v.x, s2);
            float xs2y = __shfl_sync(FULLMASK, v.y, s2);
            ax[j] = fmaf(aw2, xs2x, fmaf(aw1, xs1x, aw0 * xs0x));
            ay[j] = fmaf(aw2, xs2y, fmaf(aw1, xs1y, aw0 * xs0y));
        }
        if (lane < 21) {
            *(float4*)&yx[lane * 8 + 4*h] = make_float4(ax[0], ax[1], ax[2], ax[3]);
            *(float4*)&yy[lane * 8 + 4*h] = make_float4(ay[0], ay[1], ay[2], ay[3]);
        }
    }
    __syncwarp();

    // ---- stage 2: p[g][d0..d1] = sum_t c_t relu(y@W1+b1), 8 graphs ----
    float p0[8], p1[8];
    #pragma unroll
    for (int g = 0; g < 8; g++) { p0[g] = 0.f; p1[g] = 0.f; }

    #pragma unroll 3
    for (int t = 0; t < 21; t++) {
        const float ct = cPool[t];
        float4 qx[2], qy[2];
        #pragma unroll
        for (int q = 0; q < 2; q++) {
            qx[q] = *(const float4*)&yx[t * 8 + 4*q];
            qy[q] = *(const float4*)&yy[t * 8 + 4*q];
        }
        #pragma unroll
        for (int q = 0; q < 2; q++) {
            const float xs[4] = {qx[q].x, qx[q].y, qx[q].z, qx[q].w};
            const float ys[4] = {qy[q].x, qy[q].y, qy[q].z, qy[q].w};
            #pragma unroll
            for (int j = 0; j < 4; j++) {
                const int g = 4*q + j;
                float ha = fmaf(ys[j], w11a, fmaf(xs[j], w10a, b1a));
                ha = fmaxf(ha, 0.f);
                p0[g] = fmaf(ct, ha, p0[g]);
                float hb = fmaf(ys[j], w11b, fmaf(xs[j], w10b, b1b));
                hb = fmaxf(hb, 0.f);
                p1[g] = fmaf(ct, hb, p1[g]);
            }
        }
    }

    // ---- write warp's 8 rows of the pair A tile (bf16 hi/lo, swizzled) ----
    {
        char* const Ahi = smp + OFF_A + pair * 4096;
        char* const Alo = Ahi + 2048;
        #pragma unroll
        for (int j = 0; j < 8; j++) {
            const int row = half * 8 + j;
            const uint32_t hp = pkbf(p1[j], p0[j]);
            const float r0 = p0[j] - bflo_f(hp);
            const float r1 = p1[j] - bfhi_f(hp);
            const uint32_t lp = pkbf(r1, r0);
            const uint32_t off = (uint32_t)row * 128 + (((uint32_t)lane * 4) ^ ((row & 7) << 4));
            *(uint32_t*)(Ahi + off) = hp;
            *(uint32_t*)(Alo + off) = lp;
        }
    }

    // single wait+barrier: W2 cp.async drained AND all A tiles written
    asm volatile("cp.async.wait_group 0;" ::: "memory");
    __syncthreads();

    // ---- stage 3: pair tile out[16x128]; this warp does its n-half ----
    uint32_t ahi[4][4], alo[4][4];
    {
        const uint32_t m = lane & 15, ch = (lane >> 4);
        const uint32_t arow = m * 128;
        const uint32_t abase_hi = sbase + OFF_A + pair * 4096;
        const uint32_t abase_lo = abase_hi + 2048;
        #pragma unroll
        for (int kt = 0; kt < 4; kt++) {
            const uint32_t kb = (uint32_t)kt * 32 + ch * 16;
            const uint32_t off = arow + (kb ^ ((m & 7) << 4));
            ldsm_x4(ahi[kt], abase_hi + off);
            ldsm_x4(alo[kt], abase_lo + off);
        }
    }

    // B x4.trans lane addressing
    const uint32_t mg    = (uint32_t)lane >> 3;
    const uint32_t krow  = ((uint32_t)lane & 7) + ((mg & 1) << 3);
    const uint32_t nhalf = (mg >> 1) << 4;
    const uint32_t wbase_hi = sbase + OFF_WHI;
    const uint32_t wbase_lo = sbase + OFF_WLO;
    const int gr0 = gt0 + (lane >> 2);
    const int gr1 = gr0 + 8;
    const int ncol = (lane & 3) * 2;

    #pragma unroll
    for (int i = 0; i < 4; i++) {                   // this warp's 4 n16-tile pairs
        const int ntp = half * 4 + i;
        float d0[4] = {0.f, 0.f, 0.f, 0.f};
        float d1[4] = {0.f, 0.f, 0.f, 0.f};
        const uint32_t nb = (uint32_t)ntp * 32 + nhalf;
        #pragma unroll
        for (int kt = 0; kt < 4; kt++) {
            const uint32_t k = (uint32_t)kt * 16 + krow;
            const uint32_t off = k * 256 + (nb ^ ((k & 7) << 4));
            uint32_t bh[4], bl[4];
            ldsm_x4t(bh, wbase_hi + off);
            ldsm_x4t(bl, wbase_lo + off);
            mma16816(d0, ahi[kt], bh[0], bh[1]);
            mma16816(d1, ahi[kt], bh[2], bh[3]);
            mma16816(d0, alo[kt], bh[0], bh[1]);
            mma16816(d1, alo[kt], bh[2], bh[3]);
            mma16816(d0, ahi[kt], bl[0], bl[1]);
            mma16816(d1, ahi[kt], bl[2], bl[3]);
        }
        const int c0 = ntp * 16 + ncol;
        const float2 bb0 = __ldg((const float2*)(b2 + c0));
        const float2 bb1 = __ldg((const float2*)(b2 + c0 + 8));
        if (gr0 < G) {
            *(float2*)(out + (size_t)gr0 * 128 + c0)     = make_float2(d0[0] + bb0.x, d0[1] + bb0.y);
            *(float2*)(out + (size_t)gr0 * 128 + c0 + 8) = make_float2(d1[0] + bb1.x, d1[1] + bb1.y);
        }
        if (gr1 < G) {
            *(float2*)(out + (size_t)gr1 * 128 + c0)     = make_float2(d0[2] + bb0.x, d0[3] + bb0.y);
            *(float2*)(out + (size_t)gr1 * 128 + c0 + 8) = make_float2(d1[2] + bb1.x, d1[3] + bb1.y);
        }
    }
}

extern "C" void kernel_launch(void* const* d_in, const int* in_sizes, int n_in,
                              void* d_out, int out_size) {
    const float* x  = (const float*)d_in[0];
    const float* W1 = (const float*)d_in[1];
    const float* b1 = (const float*)d_in[2];
    const float* W2 = (const float*)d_in[3];
    const float* b2 = (const float*)d_in[4];
    float* out = (float*)d_out;

    const int G = in_sizes[0] / 42;              // graphs = B*S = 32768
    const int blocks = (G + 63) / 64;            // 64 graphs/CTA -> 512

    static int attr_set = 0;
    if (!attr_set) {
        cudaFuncSetAttribute(gnn_kernel,
                             cudaFuncAttributeMaxDynamicSharedMemorySize, DYN_SMEM);
        attr_set = 1;
    }
    gnn_kernel<<<blocks, THREADS, DYN_SMEM>>>(x, W1, b1, W2, b2, out, G);
}